// round 2
// baseline (speedup 1.0000x reference)
#include <cuda_runtime.h>

// 2-layer LSTM with top-layer feedback.
// B=4096, H=300, T=64. Per step, per cell:
//   gates[B,4H] = x@W_ih^T + h@W_hh^T + (b_ih+b_hh); i,f,g,o -> c,h update.
// Fused kernel: each block computes a [BM x BN] tile of h-space with all 4
// gates (full K=600 reduction in-block), then applies the cell nonlinearity
// and writes h/c (and y for layer 1). 128 sequential launches, graph-captured.

namespace {
constexpr int Bx = 4096;
constexpr int Hd = 300;
constexpr int Tn = 64;
constexpr int G  = 4;
constexpr int BM = 64;
constexpr int BN = 64;
constexpr int BK = 20;            // 300 = 15 * 20, no ragged K tiles
constexpr int BH = Bx * Hd;
}

// Recurrent state. h needs ping-pong (read as GEMM operand across blocks
// while being rewritten); c is element-local so in-place is safe.
__device__ float g_h0[2][BH];
__device__ float g_h1[2][BH];
__device__ float g_c0[BH];
__device__ float g_c1[BH];

__global__ void zero_state_kernel() {
  int i = blockIdx.x * blockDim.x + threadIdx.x;
  if (i < BH) {
    g_h0[0][i] = 0.f;
    g_h1[0][i] = 0.f;
    g_c0[i] = 0.f;
    g_c1[i] = 0.f;
  }
}

__device__ __forceinline__ float sigmoid_f(float v) {
  return 1.0f / (1.0f + __expf(-v));
}

__global__ __launch_bounds__(256) void lstm_cell_kernel(
    const float* __restrict__ X,      // [B, H] input (z or h1_prev or h0_new)
    const float* __restrict__ Hprev,  // [B, H] recurrent h
    const float* __restrict__ Cin,    // [B, H] cell state in (== Cout ok)
    float* __restrict__ Cout,
    float* __restrict__ Hout,
    const float* __restrict__ Wih,    // [4H, H]
    const float* __restrict__ Whh,    // [4H, H]
    const float* __restrict__ bih,    // [4H]
    const float* __restrict__ bhh,    // [4H]
    float* __restrict__ Y,            // [B, T, H] or nullptr
    int t)
{
  // +4 padding keeps 16B alignment for float4 reads (68 floats = 17*16B)
  // while breaking the k-stride store bank conflicts.
  __shared__ __align__(16) float As[BK][BM + 4];
  __shared__ __align__(16) float Bs[G][BK][BN + 4];

  const int tid = threadIdx.x;
  const int tx = tid & 15;   // n direction
  const int ty = tid >> 4;   // m direction
  const int m0 = blockIdx.x * BM;
  const int n0 = blockIdx.y * BN;

  float acc[G][16];
  #pragma unroll
  for (int g = 0; g < G; ++g)
    #pragma unroll
    for (int i = 0; i < 16; ++i) acc[g][i] = 0.f;

  #pragma unroll 1
  for (int phase = 0; phase < 2; ++phase) {
    const float* A = phase ? Hprev : X;
    const float* W = phase ? Whh : Wih;
    #pragma unroll 1
    for (int kt = 0; kt < Hd / BK; ++kt) {
      const int k0 = kt * BK;
      __syncthreads();  // previous tile fully consumed
      // A tile: [BM x BK] -> As[k][m]
      #pragma unroll
      for (int e = tid; e < BM * BK; e += 256) {
        int k = e % BK;
        int m = e / BK;
        As[k][m] = A[(m0 + m) * Hd + k0 + k];
      }
      // W tiles: 4 gates x [BN x BK] -> Bs[g][k][n]; gate g uses row g*H+n.
      #pragma unroll
      for (int e = tid; e < G * BN * BK; e += 256) {
        int k  = e % BK;
        int nm = e / BK;
        int n  = nm % BN;
        int g  = nm / BN;
        int nn = n0 + n;
        float v = 0.f;
        if (nn < Hd) v = W[(g * Hd + nn) * Hd + k0 + k];
        Bs[g][k][n] = v;
      }
      __syncthreads();
      #pragma unroll
      for (int kk = 0; kk < BK; ++kk) {
        float4 av = *reinterpret_cast<const float4*>(&As[kk][ty * 4]);
        float a[4] = {av.x, av.y, av.z, av.w};
        float b[G][4];
        #pragma unroll
        for (int g = 0; g < G; ++g) {
          float4 bv = *reinterpret_cast<const float4*>(&Bs[g][kk][tx * 4]);
          b[g][0] = bv.x; b[g][1] = bv.y; b[g][2] = bv.z; b[g][3] = bv.w;
        }
        #pragma unroll
        for (int g = 0; g < G; ++g)
          #pragma unroll
          for (int mi = 0; mi < 4; ++mi)
            #pragma unroll
            for (int ni = 0; ni < 4; ++ni)
              acc[g][mi * 4 + ni] = fmaf(a[mi], b[g][ni], acc[g][mi * 4 + ni]);
      }
    }
  }

  // Fused LSTM cell epilogue (PyTorch gate order: i, f, g, o)
  #pragma unroll
  for (int mi = 0; mi < 4; ++mi) {
    int m = m0 + ty * 4 + mi;
    #pragma unroll
    for (int ni = 0; ni < 4; ++ni) {
      int n = n0 + tx * 4 + ni;
      if (n < Hd) {
        int idx = mi * 4 + ni;
        float gi = sigmoid_f(acc[0][idx] + bih[n] + bhh[n]);
        float gf = sigmoid_f(acc[1][idx] + bih[Hd + n] + bhh[Hd + n]);
        float gg = tanhf(acc[2][idx] + bih[2 * Hd + n] + bhh[2 * Hd + n]);
        float go = sigmoid_f(acc[3][idx] + bih[3 * Hd + n] + bhh[3 * Hd + n]);
        float c = gf * Cin[m * Hd + n] + gi * gg;
        float h = go * tanhf(c);
        Cout[m * Hd + n] = c;
        Hout[m * Hd + n] = h;
        if (Y) Y[((long)m * Tn + t) * Hd + n] = h;
      }
    }
  }
}

extern "C" void kernel_launch(void* const* d_in, const int* in_sizes, int n_in,
                              void* d_out, int out_size) {
  const float* z    = (const float*)d_in[0];
  const float* Wih0 = (const float*)d_in[1];
  const float* Whh0 = (const float*)d_in[2];
  const float* bih0 = (const float*)d_in[3];
  const float* bhh0 = (const float*)d_in[4];
  const float* Wih1 = (const float*)d_in[5];
  const float* Whh1 = (const float*)d_in[6];
  const float* bih1 = (const float*)d_in[7];
  const float* bhh1 = (const float*)d_in[8];
  float* out = (float*)d_out;

  void* p;
  cudaGetSymbolAddress(&p, g_h0); float* h0b = (float*)p;
  cudaGetSymbolAddress(&p, g_h1); float* h1b = (float*)p;
  cudaGetSymbolAddress(&p, g_c0); float* c0b = (float*)p;
  cudaGetSymbolAddress(&p, g_c1); float* c1b = (float*)p;

  zero_state_kernel<<<(BH + 255) / 256, 256>>>();

  dim3 grid(Bx / BM, (Hd + BN - 1) / BN);  // 64 x 5
  for (int t = 0; t < Tn; ++t) {
    int cur = t & 1, nxt = cur ^ 1;
    const float* x0 = (t == 0) ? z : (h1b + cur * BH);
    // Layer 0: x -> h0
    lstm_cell_kernel<<<grid, 256>>>(x0, h0b + cur * BH, c0b, c0b,
                                    h0b + nxt * BH,
                                    Wih0, Whh0, bih0, bhh0, nullptr, t);
    // Layer 1: h0 -> h1 (= y_t, fed back as next x)
    lstm_cell_kernel<<<grid, 256>>>(h0b + nxt * BH, h1b + cur * BH, c1b, c1b,
                                    h1b + nxt * BH,
                                    Wih1, Whh1, bih1, bhh1, out, t);
  }
}

// round 3
// speedup vs baseline: 1.1052x; 1.1052x over previous
#include <cuda_runtime.h>

// 2-layer LSTM with top-layer feedback. B=4096, H=300, T=64.
// Per step/cell: gates[B,4H] = x@W_ih^T + h@W_hh^T + bias; i,f,g,o nonlin.
// Fused GEMM+cell kernel; f32x2 packed FMAs (FFMA2) for 2x fp32 throughput;
// 2 resident blocks/SM so co-resident blocks hide each other's load phases.

namespace {
constexpr int Bx = 4096;
constexpr int Hd = 300;
constexpr int Tn = 64;
constexpr int G  = 4;
constexpr int BM = 64;
constexpr int BN = 64;
constexpr int BK = 20;            // 300 = 15 * 20
constexpr int BH = Bx * Hd;
}

// Recurrent state: h ping-pongs (cross-block GEMM operand); c is element-local.
__device__ float g_h0[2][BH];
__device__ float g_h1[2][BH];
__device__ float g_c0[BH];
__device__ float g_c1[BH];

__global__ void zero_state_kernel() {
  int i = blockIdx.x * blockDim.x + threadIdx.x;
  if (i < BH) {
    g_h0[0][i] = 0.f;
    g_h1[0][i] = 0.f;
    g_c0[i] = 0.f;
    g_c1[i] = 0.f;
  }
}

__device__ __forceinline__ unsigned long long pack_dup(float a) {
  unsigned long long r;
  asm("mov.b64 %0, {%1, %1};" : "=l"(r) : "f"(a));
  return r;
}
__device__ __forceinline__ void fma2(unsigned long long& d,
                                     unsigned long long a,
                                     unsigned long long b) {
  asm("fma.rn.f32x2 %0, %1, %2, %0;" : "+l"(d) : "l"(a), "l"(b));
}
__device__ __forceinline__ float2 unpack2(unsigned long long v) {
  float2 r;
  asm("mov.b64 {%0, %1}, %2;" : "=f"(r.x), "=f"(r.y) : "l"(v));
  return r;
}

__device__ __forceinline__ float sigmoid_f(float v) {
  return __fdividef(1.0f, 1.0f + __expf(-v));
}
__device__ __forceinline__ float tanh_f(float v) {
  return 2.0f * __fdividef(1.0f, 1.0f + __expf(-2.0f * v)) - 1.0f;
}

__global__ __launch_bounds__(256, 2) void lstm_cell_kernel(
    const float* __restrict__ X,      // [B, H] input
    const float* __restrict__ Hprev,  // [B, H] recurrent h
    const float* __restrict__ Cin,    // [B, H] (== Cout is fine)
    float* __restrict__ Cout,
    float* __restrict__ Hout,
    const float* __restrict__ Wih,    // [4H, H]
    const float* __restrict__ Whh,    // [4H, H]
    const float* __restrict__ bih,    // [4H]
    const float* __restrict__ bhh,    // [4H]
    float* __restrict__ Y,            // [B, T, H] or nullptr
    int t)
{
  // +4 pad keeps 16B alignment (68 floats = 17*16B) and breaks store conflicts.
  __shared__ __align__(16) float As[BK][BM + 4];
  __shared__ __align__(16) float Bs[G][BK][BN + 4];

  const int tid = threadIdx.x;
  const int tx = tid & 15;   // n direction (x4)
  const int ty = tid >> 4;   // m direction (x4)
  const int m0 = blockIdx.x * BM;
  const int n0 = blockIdx.y * BN;

  // acc[g][mi][p]: p selects f32x2 pair over n = tx*4 + 2p + {0,1}
  unsigned long long acc[G][4][2];
  #pragma unroll
  for (int g = 0; g < G; ++g)
    #pragma unroll
    for (int mi = 0; mi < 4; ++mi) {
      acc[g][mi][0] = 0ull;
      acc[g][mi][1] = 0ull;
    }

  #pragma unroll 1
  for (int phase = 0; phase < 2; ++phase) {
    const float* A = phase ? Hprev : X;
    const float* W = phase ? Whh : Wih;
    #pragma unroll 1
    for (int kt = 0; kt < Hd / BK; ++kt) {
      const int k0 = kt * BK;
      __syncthreads();  // previous tile fully consumed
      // A tile: [BM x BK] -> As[k][m]
      #pragma unroll
      for (int e = tid; e < BM * BK; e += 256) {
        int k = e % BK;
        int m = e / BK;
        As[k][m] = A[(m0 + m) * Hd + k0 + k];
      }
      // W tiles: 4 gates x [BN x BK] -> Bs[g][k][n]
      #pragma unroll
      for (int e = tid; e < G * BN * BK; e += 256) {
        int k  = e % BK;
        int nm = e / BK;
        int n  = nm % BN;
        int g  = nm / BN;
        int nn = n0 + n;
        float v = 0.f;
        if (nn < Hd) v = W[(g * Hd + nn) * Hd + k0 + k];
        Bs[g][k][n] = v;
      }
      __syncthreads();
      #pragma unroll
      for (int kk = 0; kk < BK; ++kk) {
        float4 av = *reinterpret_cast<const float4*>(&As[kk][ty * 4]);
        unsigned long long aa[4] = {pack_dup(av.x), pack_dup(av.y),
                                    pack_dup(av.z), pack_dup(av.w)};
        #pragma unroll
        for (int g = 0; g < G; ++g) {
          ulonglong2 bv =
              *reinterpret_cast<const ulonglong2*>(&Bs[g][kk][tx * 4]);
          #pragma unroll
          for (int mi = 0; mi < 4; ++mi) {
            fma2(acc[g][mi][0], aa[mi], bv.x);
            fma2(acc[g][mi][1], aa[mi], bv.y);
          }
        }
      }
    }
  }

  // Fused LSTM cell epilogue (gate order: i, f, g, o)
  #pragma unroll
  for (int mi = 0; mi < 4; ++mi) {
    int m = m0 + ty * 4 + mi;
    #pragma unroll
    for (int p = 0; p < 2; ++p) {
      float2 vi = unpack2(acc[0][mi][p]);
      float2 vf = unpack2(acc[1][mi][p]);
      float2 vg = unpack2(acc[2][mi][p]);
      float2 vo = unpack2(acc[3][mi][p]);
      float gi[2] = {vi.x, vi.y};
      float gf[2] = {vf.x, vf.y};
      float gg[2] = {vg.x, vg.y};
      float go[2] = {vo.x, vo.y};
      #pragma unroll
      for (int l = 0; l < 2; ++l) {
        int n = n0 + tx * 4 + p * 2 + l;
        if (n < Hd) {
          float i_ = sigmoid_f(gi[l] + bih[n] + bhh[n]);
          float f_ = sigmoid_f(gf[l] + bih[Hd + n] + bhh[Hd + n]);
          float g_ = tanh_f(gg[l] + bih[2 * Hd + n] + bhh[2 * Hd + n]);
          float o_ = sigmoid_f(go[l] + bih[3 * Hd + n] + bhh[3 * Hd + n]);
          float c = f_ * Cin[m * Hd + n] + i_ * g_;
          float h = o_ * tanh_f(c);
          Cout[m * Hd + n] = c;
          Hout[m * Hd + n] = h;
          if (Y) Y[((long)m * Tn + t) * Hd + n] = h;
        }
      }
    }
  }
}

extern "C" void kernel_launch(void* const* d_in, const int* in_sizes, int n_in,
                              void* d_out, int out_size) {
  const float* z    = (const float*)d_in[0];
  const float* Wih0 = (const float*)d_in[1];
  const float* Whh0 = (const float*)d_in[2];
  const float* bih0 = (const float*)d_in[3];
  const float* bhh0 = (const float*)d_in[4];
  const float* Wih1 = (const float*)d_in[5];
  const float* Whh1 = (const float*)d_in[6];
  const float* bih1 = (const float*)d_in[7];
  const float* bhh1 = (const float*)d_in[8];
  float* out = (float*)d_out;

  void* p;
  cudaGetSymbolAddress(&p, g_h0); float* h0b = (float*)p;
  cudaGetSymbolAddress(&p, g_h1); float* h1b = (float*)p;
  cudaGetSymbolAddress(&p, g_c0); float* c0b = (float*)p;
  cudaGetSymbolAddress(&p, g_c1); float* c1b = (float*)p;

  zero_state_kernel<<<(BH + 255) / 256, 256>>>();

  dim3 grid(Bx / BM, (Hd + BN - 1) / BN);  // 64 x 5
  for (int t = 0; t < Tn; ++t) {
    int cur = t & 1, nxt = cur ^ 1;
    const float* x0 = (t == 0) ? z : (h1b + cur * BH);
    // Layer 0: x -> h0
    lstm_cell_kernel<<<grid, 256>>>(x0, h0b + cur * BH, c0b, c0b,
                                    h0b + nxt * BH,
                                    Wih0, Whh0, bih0, bhh0, nullptr, t);
    // Layer 1: h0 -> h1 (= y_t, fed back as next x)
    lstm_cell_kernel<<<grid, 256>>>(h0b + nxt * BH, h1b + cur * BH, c1b, c1b,
                                    h1b + nxt * BH,
                                    Wih1, Whh1, bih1, bhh1, out, t);
  }
}

// round 8
// speedup vs baseline: 2.3030x; 2.0838x over previous
#include <cuda_runtime.h>
#include <cuda_bf16.h>
#include <cstdint>

// 2-layer LSTM, B=4096, H=300, T=64, via tcgen05 bf16-split MMA.
// Per cell: gates[4096,1200] = X@Wih^T + H@Whh^T (+bias), D accumulated in
// TMEM fp32 over 3 split products (hi*hi, hi*lo, lo*hi). Weights are
// pre-split and gate-interleaved (col n = 4*h + gate) so the LSTM epilogue
// is local to the CTA's N-tile. Activations are stored pre-split in bf16.
//
// tcgen05 is only legal on the arch-specific target (sm_103a/sm_100a). The
// harness also runs a non-'a' compilation pass, so every tcgen05 use is
// gated on the arch-feature macros; the #else branch is a functionally
// identical SIMT fallback reading the same smem tiles.

#if defined(__CUDA_ARCH_FEAT_SM103_ALL) || defined(__CUDA_ARCH_FEAT_SM100_ALL) || \
    defined(__CUDA_ARCH_FEAT_SM101_ALL) ||                                        \
    (defined(__CUDA_ARCH_FAMILY_SPECIFIC__) && (__CUDA_ARCH_FAMILY_SPECIFIC__ >= 1000))
#define LSTM_TC 1
#else
#define LSTM_TC 0
#endif

#define SW128(o) ((o) ^ (((o) >> 3) & 0x70))

namespace {
constexpr int Bx = 4096, Hd = 300, Tn = 64;
constexpr int Kp = 320;              // K per phase, padded (300 -> 5*64)
constexpr int Np = 1200;             // 4*Hd, gate-interleaved
constexpr int BM = 128, BN = 120, BK = 64;
constexpr int NKT = Kp / BK;         // 5
constexpr int NMT = Bx / BM;         // 32
constexpr int NNT = Np / BN;         // 10
constexpr unsigned IDESC = (1u << 4)      // dtype F32
                         | (1u << 7)      // atype BF16
                         | (1u << 10)     // btype BF16
                         | ((BN / 8) << 17)
                         | ((BM / 16) << 24);
constexpr unsigned long long DESC_BASE =  // SW128, Blackwell, SBO=64, LBO=1
    (2ull << 61) | (1ull << 46) | (64ull << 32) | (1ull << 16);
// dynamic smem layout (bases 1024-aligned for descriptors)
constexpr int SM_TMEM = 0;
constexpr int SM_MBAR = 8;
constexpr int SM_AHI  = 1024;
constexpr int SM_ALO  = SM_AHI + BM * 128;   // 17408
constexpr int SM_BHI  = SM_ALO + BM * 128;   // 33792
constexpr int SM_BLO  = SM_BHI + BN * 128;   // 49152
constexpr int SM_BIAS = SM_BLO + BN * 128;   // 64512
constexpr int SM_TOTAL = SM_BIAS + BN * 4 + 64;
}

// ---- persistent device state -------------------------------------------
__device__ __align__(1024) __nv_bfloat16 g_WHi[4][Np * Kp];  // ih0,hh0,ih1,hh1
__device__ __align__(1024) __nv_bfloat16 g_WLo[4][Np * Kp];
__device__ float g_bias[2][Np];
__device__ __align__(1024) __nv_bfloat16 g_zHi[Bx * Kp];
__device__ __align__(1024) __nv_bfloat16 g_zLo[Bx * Kp];
__device__ __align__(1024) __nv_bfloat16 g_hHi[2][2][Bx * Kp];  // [layer][buf]
__device__ __align__(1024) __nv_bfloat16 g_hLo[2][2][Bx * Kp];
__device__ float g_c[2][Hd * Bx];  // [cell][h*Bx + m] (transposed, coalesced)

// ---- small helpers ------------------------------------------------------
__device__ __forceinline__ float sigmoid_f(float v) {
  return __fdividef(1.0f, 1.0f + __expf(-v));
}
__device__ __forceinline__ float tanh_f(float v) {
  return 2.0f * __fdividef(1.0f, 1.0f + __expf(-2.0f * v)) - 1.0f;
}

#if LSTM_TC
__device__ __forceinline__ void mma_f16_ss(uint32_t d, unsigned long long da,
                                           unsigned long long db, uint32_t en) {
  asm volatile(
      "{\n\t.reg .pred p;\n\tsetp.ne.u32 p, %4, 0;\n\t"
      "tcgen05.mma.cta_group::1.kind::f16 [%0], %1, %2, %3, {%5, %5, %5, %5}, p;\n\t}"
      :: "r"(d), "l"(da), "l"(db), "r"(IDESC), "r"(en), "r"(0u) : "memory");
}

__device__ __forceinline__ void mbar_wait(uint32_t mbar, uint32_t parity) {
  uint32_t done;
  asm volatile(
      "{\n\t.reg .pred p;\n\t"
      "mbarrier.try_wait.parity.acquire.cta.shared::cta.b64 p, [%1], %2;\n\t"
      "selp.b32 %0, 1, 0, p;\n\t}"
      : "=r"(done) : "r"(mbar), "r"(parity) : "memory");
  if (!done) {
    asm volatile(
        "{\n\t.reg .pred P1;\n\t"
        "W_%=:\n\t"
        "mbarrier.try_wait.parity.acquire.cta.shared::cta.b64 P1, [%0], %1, 0x989680;\n\t"
        "@P1 bra.uni D_%=;\n\t"
        "bra.uni W_%=;\n\t"
        "D_%=:\n\t}"
        :: "r"(mbar), "r"(parity) : "memory");
  }
}

__device__ __forceinline__ void ldtm_x32(uint32_t* r, uint32_t a) {
  asm volatile(
      "tcgen05.ld.sync.aligned.32x32b.x32.b32 "
      "{%0,%1,%2,%3,%4,%5,%6,%7,%8,%9,%10,%11,%12,%13,%14,%15,"
      "%16,%17,%18,%19,%20,%21,%22,%23,%24,%25,%26,%27,%28,%29,%30,%31}, [%32];"
      : "=r"(r[0]), "=r"(r[1]), "=r"(r[2]), "=r"(r[3]), "=r"(r[4]), "=r"(r[5]),
        "=r"(r[6]), "=r"(r[7]), "=r"(r[8]), "=r"(r[9]), "=r"(r[10]), "=r"(r[11]),
        "=r"(r[12]), "=r"(r[13]), "=r"(r[14]), "=r"(r[15]), "=r"(r[16]),
        "=r"(r[17]), "=r"(r[18]), "=r"(r[19]), "=r"(r[20]), "=r"(r[21]),
        "=r"(r[22]), "=r"(r[23]), "=r"(r[24]), "=r"(r[25]), "=r"(r[26]),
        "=r"(r[27]), "=r"(r[28]), "=r"(r[29]), "=r"(r[30]), "=r"(r[31])
      : "r"(a));
}
__device__ __forceinline__ void ldtm_x16(uint32_t* r, uint32_t a) {
  asm volatile(
      "tcgen05.ld.sync.aligned.32x32b.x16.b32 "
      "{%0,%1,%2,%3,%4,%5,%6,%7,%8,%9,%10,%11,%12,%13,%14,%15}, [%16];"
      : "=r"(r[0]), "=r"(r[1]), "=r"(r[2]), "=r"(r[3]), "=r"(r[4]), "=r"(r[5]),
        "=r"(r[6]), "=r"(r[7]), "=r"(r[8]), "=r"(r[9]), "=r"(r[10]), "=r"(r[11]),
        "=r"(r[12]), "=r"(r[13]), "=r"(r[14]), "=r"(r[15])
      : "r"(a));
}
__device__ __forceinline__ void ldtm_x8(uint32_t* r, uint32_t a) {
  asm volatile(
      "tcgen05.ld.sync.aligned.32x32b.x8.b32 {%0,%1,%2,%3,%4,%5,%6,%7}, [%8];"
      : "=r"(r[0]), "=r"(r[1]), "=r"(r[2]), "=r"(r[3]), "=r"(r[4]), "=r"(r[5]),
        "=r"(r[6]), "=r"(r[7])
      : "r"(a));
}
#endif  // LSTM_TC

// ---- prep: split/pad weights, biases, z; zero state ---------------------
__global__ void prep_kernel(const float* __restrict__ z,
                            const float* __restrict__ Wih0,
                            const float* __restrict__ Whh0,
                            const float* __restrict__ bih0,
                            const float* __restrict__ bhh0,
                            const float* __restrict__ Wih1,
                            const float* __restrict__ Whh1,
                            const float* __restrict__ bih1,
                            const float* __restrict__ bhh1) {
  const int stride = gridDim.x * blockDim.x;
  const int g0 = blockIdx.x * blockDim.x + threadIdx.x;
  const float* Ws[4] = {Wih0, Whh0, Wih1, Whh1};
  for (int idx = g0; idx < 4 * Np * Kp; idx += stride) {
    int k = idx % Kp;
    int rr = idx / Kp;
    int n = rr % Np;
    int mi = rr / Np;
    int h = n >> 2, gg = n & 3;
    float w = (k < Hd) ? Ws[mi][(gg * Hd + h) * Hd + k] : 0.f;
    __nv_bfloat16 hi = __float2bfloat16(w);
    g_WHi[mi][n * Kp + k] = hi;
    g_WLo[mi][n * Kp + k] = __float2bfloat16(w - __bfloat162float(hi));
  }
  for (int idx = g0; idx < 2 * Np; idx += stride) {
    int n = idx % Np, cell = idx / Np;
    int h = n >> 2, gg = n & 3;
    g_bias[cell][n] = cell ? (bih1[gg * Hd + h] + bhh1[gg * Hd + h])
                           : (bih0[gg * Hd + h] + bhh0[gg * Hd + h]);
  }
  for (int idx = g0; idx < Bx * Kp; idx += stride) {
    int k = idx % Kp, m = idx / Kp;
    float v = (k < Hd) ? z[m * Hd + k] : 0.f;
    __nv_bfloat16 hi = __float2bfloat16(v);
    g_zHi[idx] = hi;
    g_zLo[idx] = __float2bfloat16(v - __bfloat162float(hi));
    __nv_bfloat16 zz = __float2bfloat16(0.f);
    g_hHi[0][0][idx] = zz; g_hLo[0][0][idx] = zz;
    g_hHi[0][1][idx] = zz; g_hLo[0][1][idx] = zz;
    g_hHi[1][0][idx] = zz; g_hLo[1][0][idx] = zz;
    g_hHi[1][1][idx] = zz; g_hLo[1][1][idx] = zz;
  }
  for (int idx = g0; idx < Hd * Bx; idx += stride) {
    g_c[0][idx] = 0.f;
    g_c[1][idx] = 0.f;
  }
}

// ---- epilogue helper: 4 cols per h (i,f,g,o interleaved) ----------------
__device__ __forceinline__ void cell_cols(const uint32_t* r, int nh, int cb,
                                          int n0, int m, const float* bsm,
                                          float* __restrict__ C,
                                          __nv_bfloat16* __restrict__ HoHi,
                                          __nv_bfloat16* __restrict__ HoLo,
                                          float* __restrict__ Y, int t) {
  #pragma unroll
  for (int j = 0; j < nh; ++j) {
    int col = cb + j * 4;
    int hg = (n0 + col) >> 2;
    float vi = __uint_as_float(r[j * 4 + 0]) + bsm[col + 0];
    float vf = __uint_as_float(r[j * 4 + 1]) + bsm[col + 1];
    float vg = __uint_as_float(r[j * 4 + 2]) + bsm[col + 2];
    float vo = __uint_as_float(r[j * 4 + 3]) + bsm[col + 3];
    float i_ = sigmoid_f(vi);
    float f_ = sigmoid_f(vf);
    float g_ = tanh_f(vg);
    float o_ = sigmoid_f(vo);
    size_t ci = (size_t)hg * Bx + m;
    float c = f_ * C[ci] + i_ * g_;
    float h = o_ * tanh_f(c);
    C[ci] = c;
    __nv_bfloat16 hi = __float2bfloat16(h);
    HoHi[(size_t)m * Kp + hg] = hi;
    HoLo[(size_t)m * Kp + hg] = __float2bfloat16(h - __bfloat162float(hi));
    if (Y) Y[(size_t)m * (Tn * Hd) + (size_t)t * Hd + hg] = h;
  }
}

// ---- main fused GEMM + LSTM-cell kernel ---------------------------------
__global__ __launch_bounds__(256)
void lstm_tc_kernel(const __nv_bfloat16* __restrict__ Xhi,
                    const __nv_bfloat16* __restrict__ Xlo,
                    const __nv_bfloat16* __restrict__ Rhi,
                    const __nv_bfloat16* __restrict__ Rlo,
                    const __nv_bfloat16* __restrict__ WihHi,
                    const __nv_bfloat16* __restrict__ WihLo,
                    const __nv_bfloat16* __restrict__ WhhHi,
                    const __nv_bfloat16* __restrict__ WhhLo,
                    const float* __restrict__ bias, float* __restrict__ C,
                    __nv_bfloat16* __restrict__ HoHi,
                    __nv_bfloat16* __restrict__ HoLo, float* __restrict__ Y,
                    int t) {
  extern __shared__ __align__(1024) char smem[];
  const uint32_t sbase = (uint32_t)__cvta_generic_to_shared(smem);
  const int tid = threadIdx.x;
  const int wid = tid >> 5, lid = tid & 31;
  const int m0 = blockIdx.x * BM;
  const int n0 = blockIdx.y * BN;

#if LSTM_TC
  if (wid == 0) {
    asm volatile(
        "tcgen05.alloc.cta_group::1.sync.aligned.shared::cta.b32 [%0], %1;"
        :: "r"(sbase + SM_TMEM), "r"(128u) : "memory");
  }
  if (tid == 0) {
    asm volatile("mbarrier.init.shared.b64 [%0], 1;"
                 :: "r"(sbase + SM_MBAR) : "memory");
  }
#else
  // Fallback: thread (row = tid>>1, half = tid&1) owns D[row][half*60 .. +59].
  float facc[60];
  #pragma unroll
  for (int i = 0; i < 60; ++i) facc[i] = 0.f;
  const int f_row = tid >> 1;
  const int f_ch  = tid & 1;
#endif
  if (tid < BN) {
    ((float*)(smem + SM_BIAS))[tid] = bias[n0 + tid];
  }
  __syncthreads();

#if LSTM_TC
  uint32_t tmem_base;
  asm volatile("ld.shared.b32 %0, [%1];"
               : "=r"(tmem_base) : "r"(sbase + SM_TMEM));
  const uint32_t dD = tmem_base;  // D in cols [0,120)
  uint32_t en = 0;                // first MMA initializes D
  int par = 0;
#endif

  #pragma unroll 1
  for (int ph = 0; ph < 2; ++ph) {
    const __nv_bfloat16* Ahi = ph ? Rhi : Xhi;
    const __nv_bfloat16* Alo = ph ? Rlo : Xlo;
    const __nv_bfloat16* Bh = ph ? WhhHi : WihHi;
    const __nv_bfloat16* Bl = ph ? WhhLo : WihLo;
    #pragma unroll 1
    for (int kt = 0; kt < NKT; ++kt) {
      const int k0 = kt * BK;
      __syncthreads();  // previous tile fully consumed
      // A tiles: 128 rows x 128B (hi & lo)
      for (int e = tid; e < BM * 8; e += 256) {
        int r = e >> 3, u = e & 7;
        const char* sh = (const char*)(Ahi + (size_t)(m0 + r) * Kp + k0);
        const char* sl = (const char*)(Alo + (size_t)(m0 + r) * Kp + k0);
        uint32_t off = SW128(r * 128 + u * 16);
        *(uint4*)(smem + SM_AHI + off) = *(const uint4*)(sh + u * 16);
        *(uint4*)(smem + SM_ALO + off) = *(const uint4*)(sl + u * 16);
      }
      // B tiles: 120 rows x 128B (hi & lo)
      for (int e = tid; e < BN * 8; e += 256) {
        int r = e >> 3, u = e & 7;
        const char* sh = (const char*)(Bh + (size_t)(n0 + r) * Kp + k0);
        const char* sl = (const char*)(Bl + (size_t)(n0 + r) * Kp + k0);
        uint32_t off = SW128(r * 128 + u * 16);
        *(uint4*)(smem + SM_BHI + off) = *(const uint4*)(sh + u * 16);
        *(uint4*)(smem + SM_BLO + off) = *(const uint4*)(sl + u * 16);
      }
      __syncthreads();
#if LSTM_TC
      if (tid == 0) {
        asm volatile("fence.proxy.async.shared::cta;" ::: "memory");
        unsigned long long dAh = DESC_BASE | (((sbase + SM_AHI) >> 4) & 0x3FFF);
        unsigned long long dAl = DESC_BASE | (((sbase + SM_ALO) >> 4) & 0x3FFF);
        unsigned long long dBh = DESC_BASE | (((sbase + SM_BHI) >> 4) & 0x3FFF);
        unsigned long long dBl = DESC_BASE | (((sbase + SM_BLO) >> 4) & 0x3FFF);
        #pragma unroll
        for (int k16 = 0; k16 < 4; ++k16) {
          unsigned long long off = k16 * 2;  // 32B in 16B units
          mma_f16_ss(dD, dAh + off, dBh + off, en);
          en = 1;
          mma_f16_ss(dD, dAh + off, dBl + off, 1);
          mma_f16_ss(dD, dAl + off, dBh + off, 1);
        }
        asm volatile(
            "tcgen05.commit.cta_group::1.mbarrier::arrive::one.shared::cluster.b64 [%0];"
            :: "r"(sbase + SM_MBAR) : "memory");
      }
      mbar_wait(sbase + SM_MBAR, (uint32_t)par);
      par ^= 1;
#else
      // Fallback SIMT accumulate from the same swizzled smem tiles.
      for (int k = 0; k < BK; ++k) {
        uint32_t ao = SW128(f_row * 128 + k * 2);
        float a = __bfloat162float(*(const __nv_bfloat16*)(smem + SM_AHI + ao)) +
                  __bfloat162float(*(const __nv_bfloat16*)(smem + SM_ALO + ao));
        #pragma unroll 4
        for (int c = 0; c < 60; ++c) {
          int bn = f_ch * 60 + c;
          uint32_t bo = SW128(bn * 128 + k * 2);
          float b = __bfloat162float(*(const __nv_bfloat16*)(smem + SM_BHI + bo)) +
                    __bfloat162float(*(const __nv_bfloat16*)(smem + SM_BLO + bo));
          facc[c] = fmaf(a, b, facc[c]);
        }
      }
#endif
    }
  }

#if LSTM_TC
  // ---- fused LSTM epilogue (warps 0-3 read their TMEM subpartitions) ----
  if (wid < 4) {
    asm volatile("tcgen05.fence::after_thread_sync;" ::: "memory");
    const int m = m0 + wid * 32 + lid;
    const float* bsm = (const float*)(smem + SM_BIAS);
    uint32_t r[32];
    #pragma unroll
    for (int cbi = 0; cbi < 3; ++cbi) {
      ldtm_x32(r, dD + cbi * 32);
      asm volatile("tcgen05.wait::ld.sync.aligned;" ::: "memory");
      cell_cols(r, 8, cbi * 32, n0, m, bsm, C, HoHi, HoLo, Y, t);
    }
    ldtm_x16(r, dD + 96);
    asm volatile("tcgen05.wait::ld.sync.aligned;" ::: "memory");
    cell_cols(r, 4, 96, n0, m, bsm, C, HoHi, HoLo, Y, t);
    ldtm_x8(r, dD + 112);
    asm volatile("tcgen05.wait::ld.sync.aligned;" ::: "memory");
    cell_cols(r, 2, 112, n0, m, bsm, C, HoHi, HoLo, Y, t);
  }
  __syncthreads();
  if (tid == 0) {
    asm volatile("mbarrier.inval.shared.b64 [%0];"
                 :: "r"(sbase + SM_MBAR) : "memory");
  }
  if (wid == 0) {
    asm volatile("tcgen05.relinquish_alloc_permit.cta_group::1.sync.aligned;");
    asm volatile("tcgen05.dealloc.cta_group::1.sync.aligned.b32 %0, %1;"
                 :: "r"(tmem_base), "r"(128u));
  }
#else
  // Fallback epilogue straight from the per-thread accumulators (15 h-groups).
  {
    const float* bsm = (const float*)(smem + SM_BIAS);
    cell_cols((const uint32_t*)facc, 15, f_ch * 60, n0, m0 + f_row, bsm, C,
              HoHi, HoLo, Y, t);
  }
  (void)wid; (void)lid;
#endif
}

// ---- host side ----------------------------------------------------------
extern "C" void kernel_launch(void* const* d_in, const int* in_sizes, int n_in,
                              void* d_out, int out_size) {
  const float* z    = (const float*)d_in[0];
  const float* Wih0 = (const float*)d_in[1];
  const float* Whh0 = (const float*)d_in[2];
  const float* bih0 = (const float*)d_in[3];
  const float* bhh0 = (const float*)d_in[4];
  const float* Wih1 = (const float*)d_in[5];
  const float* Whh1 = (const float*)d_in[6];
  const float* bih1 = (const float*)d_in[7];
  const float* bhh1 = (const float*)d_in[8];
  float* out = (float*)d_out;

  cudaFuncSetAttribute(lstm_tc_kernel,
                       cudaFuncAttributeMaxDynamicSharedMemorySize, SM_TOTAL);

  void* p;
  cudaGetSymbolAddress(&p, g_WHi);  __nv_bfloat16* wHi = (__nv_bfloat16*)p;
  cudaGetSymbolAddress(&p, g_WLo);  __nv_bfloat16* wLo = (__nv_bfloat16*)p;
  cudaGetSymbolAddress(&p, g_bias); float* bias = (float*)p;
  cudaGetSymbolAddress(&p, g_zHi);  __nv_bfloat16* zHi = (__nv_bfloat16*)p;
  cudaGetSymbolAddress(&p, g_zLo);  __nv_bfloat16* zLo = (__nv_bfloat16*)p;
  cudaGetSymbolAddress(&p, g_hHi);  __nv_bfloat16* hHi = (__nv_bfloat16*)p;
  cudaGetSymbolAddress(&p, g_hLo);  __nv_bfloat16* hLo = (__nv_bfloat16*)p;
  cudaGetSymbolAddress(&p, g_c);    float* cst = (float*)p;

  const size_t WS = (size_t)Np * Kp;   // one weight matrix
  const size_t AS = (size_t)Bx * Kp;   // one activation buffer
  const size_t CS = (size_t)Hd * Bx;

  prep_kernel<<<1024, 256>>>(z, Wih0, Whh0, bih0, bhh0, Wih1, Whh1, bih1, bhh1);

  dim3 grid(NMT, NNT);  // 32 x 10
  for (int t = 0; t < Tn; ++t) {
    int cur = t & 1, nxt = cur ^ 1;
    // layer-0 input: z at t=0, else fed-back h1(t-1)
    const __nv_bfloat16* x0hi = (t == 0) ? zHi : hHi + (2 + cur) * AS;
    const __nv_bfloat16* x0lo = (t == 0) ? zLo : hLo + (2 + cur) * AS;
    lstm_tc_kernel<<<grid, 256, SM_TOTAL>>>(
        x0hi, x0lo, hHi + cur * AS, hLo + cur * AS,
        wHi + 0 * WS, wLo + 0 * WS, wHi + 1 * WS, wLo + 1 * WS,
        bias, cst, hHi + nxt * AS, hLo + nxt * AS, nullptr, t);
    lstm_tc_kernel<<<grid, 256, SM_TOTAL>>>(
        hHi + nxt * AS, hLo + nxt * AS, hHi + (2 + cur) * AS, hLo + (2 + cur) * AS,
        wHi + 2 * WS, wLo + 2 * WS, wHi + 3 * WS, wLo + 3 * WS,
        bias + Np, cst + CS, hHi + (2 + nxt) * AS, hLo + (2 + nxt) * AS, out, t);
  }
}